// round 14
// baseline (speedup 1.0000x reference)
#include <cuda_runtime.h>
#include <cuda_bf16.h>
#include <math.h>

// Problem constants
#define BB   128
#define TT   64
#define EE   512
#define HH   512
#define VV   10000
#define FIN  2048
#define G3   1536   // 3*H
#define NBLK 128    // persistent kernel grid size

// ---------------- scratch (device globals; no allocations allowed) ----------
__device__ float g_P[TT * BB * 2048];      // precomputed x-parts [T,B,2048]
__device__ float g_fpre[BB * EE];
__device__ float g_feats[BB * EE];         // full precision
__device__ float g_Mmat[G3 * 1024];        // gru_Wih @ comb_W (fp32 result)
__device__ float g_WpH[2048 * 512];        // [attn_Wh ; gru_Whh], tf32-rounded
__device__ float g_M2[G3 * 512];           // M[:,512:], tf32-rounded
__device__ float g_bias0[2048];            // [attn_b ; gru_Wih@comb_b + gru_bih]
__device__ float g_S[BB * 2048];           // per-step: [attn scores ; gh]
__device__ float g_applied[BB * EE];       // tf32-rounded
__device__ float g_h[BB * HH];             // hidden state, full precision
__device__ float g_hR[BB * HH];            // hidden state, tf32-rounded
__device__ unsigned g_bar_count = 0;
__device__ unsigned g_bar_gen   = 0;

// bf16 split operands for the big legacy-mma GEMMs
__device__ __nv_bfloat16 g_combWThi[1024 * 512], g_combWTlo[1024 * 512];
__device__ __nv_bfloat16 g_Wihhi[G3 * 512],      g_Wihlo[G3 * 512];
__device__ __nv_bfloat16 g_Xhi[TT * BB * EE],    g_Xlo[TT * BB * EE];
__device__ __nv_bfloat16 g_WpXhi[2048 * 512],    g_WpXlo[2048 * 512];
__device__ __nv_bfloat16 g_outWhi[VV * 512],     g_outWlo[VV * 512];
__device__ __nv_bfloat16 g_hshi[TT * BB * HH],   g_hslo[TT * BB * HH];

// ---------------- helpers ----------------------------------------------------
__device__ __forceinline__ unsigned f2tf32(float x) {
    unsigned r;
    asm("cvt.rna.tf32.f32 %0, %1;" : "=r"(r) : "f"(x));
    return r;
}
__device__ __forceinline__ float rtf(float x) {
    return __uint_as_float(f2tf32(x));
}
__device__ __forceinline__ void split2(float v, __nv_bfloat16* hi, __nv_bfloat16* lo) {
    __nv_bfloat16 h = __float2bfloat16(v);
    *hi = h;
    *lo = __float2bfloat16(v - __bfloat162float(h));
}

__device__ __forceinline__ float block_reduce_sum(float v) {
    __shared__ float buf[32];
    int tid = threadIdx.x, lane = tid & 31, wid = tid >> 5;
    int nw = (blockDim.x + 31) >> 5;
    #pragma unroll
    for (int o = 16; o > 0; o >>= 1) v += __shfl_xor_sync(0xFFFFFFFFu, v, o);
    if (lane == 0) buf[wid] = v;
    __syncthreads();
    float r = (tid < nw) ? buf[tid] : 0.0f;
    if (wid == 0) {
        #pragma unroll
        for (int o = 16; o > 0; o >>= 1) r += __shfl_xor_sync(0xFFFFFFFFu, r, o);
        if (lane == 0) buf[0] = r;
    }
    __syncthreads();
    r = buf[0];
    __syncthreads();
    return r;
}

__device__ __forceinline__ float block_reduce_max(float v) {
    __shared__ float buf[32];
    int tid = threadIdx.x, lane = tid & 31, wid = tid >> 5;
    int nw = (blockDim.x + 31) >> 5;
    #pragma unroll
    for (int o = 16; o > 0; o >>= 1) v = fmaxf(v, __shfl_xor_sync(0xFFFFFFFFu, v, o));
    if (lane == 0) buf[wid] = v;
    __syncthreads();
    float r = (tid < nw) ? buf[tid] : -3.0e38f;
    if (wid == 0) {
        #pragma unroll
        for (int o = 16; o > 0; o >>= 1) r = fmaxf(r, __shfl_xor_sync(0xFFFFFFFFu, r, o));
        if (lane == 0) buf[0] = r;
    }
    __syncthreads();
    r = buf[0];
    __syncthreads();
    return r;
}

// cp.async helpers
__device__ __forceinline__ void cp16(float* dst, const float* src) {
    unsigned d = (unsigned)__cvta_generic_to_shared(dst);
    asm volatile("cp.async.cg.shared.global [%0], [%1], 16;" :: "r"(d), "l"(src));
}
__device__ __forceinline__ void cpA(unsigned dst_smem, const void* src) {
    asm volatile("cp.async.cg.shared.global [%0], [%1], 16;" :: "r"(dst_smem), "l"(src));
}
__device__ __forceinline__ void cpAz(unsigned dst_smem, const void* src, bool p) {
    int sz = p ? 16 : 0;
    asm volatile("cp.async.cg.shared.global [%0], [%1], 16, %2;" :: "r"(dst_smem), "l"(src), "r"(sz));
}
#define CP_COMMIT asm volatile("cp.async.commit_group;")
#define CP_WAIT1  asm volatile("cp.async.wait_group 1;")
#define CP_WAIT0  asm volatile("cp.async.wait_group 0;")

#define MMA_TF32(d0,d1,d2,d3,a0,a1,a2,a3,b0,b1)                          \
    asm volatile("mma.sync.aligned.m16n8k8.row.col.f32.tf32.tf32.f32 "   \
        "{%0,%1,%2,%3},{%4,%5,%6,%7},{%8,%9},{%0,%1,%2,%3};"             \
        : "+f"(d0), "+f"(d1), "+f"(d2), "+f"(d3)                         \
        : "r"(a0), "r"(a1), "r"(a2), "r"(a3), "r"(b0), "r"(b1))

#define MMA_BF16(d0,d1,d2,d3,a0,a1,a2,a3,b0,b1)                          \
    asm volatile("mma.sync.aligned.m16n8k16.row.col.f32.bf16.bf16.f32 "  \
        "{%0,%1,%2,%3},{%4,%5,%6,%7},{%8,%9},{%0,%1,%2,%3};"             \
        : "+f"(d0), "+f"(d1), "+f"(d2), "+f"(d3)                         \
        : "r"(a0), "r"(a1), "r"(a2), "r"(a3), "r"(b0), "r"(b1))

// Software grid barrier (all NBLK blocks co-resident: 1 CTA/SM, NBLK=128<=148)
__device__ __forceinline__ void grid_bar() {
    __syncthreads();
    if (threadIdx.x == 0) {
        __threadfence();
        unsigned target = *(volatile unsigned*)&g_bar_gen + 1u;
        unsigned old = atomicAdd(&g_bar_count, 1u);
        if (old == NBLK - 1) {
            g_bar_count = 0;
            __threadfence();
            atomicExch(&g_bar_gen, target);
        } else {
            while (*(volatile unsigned*)&g_bar_gen < target) __nanosleep(64);
        }
        __threadfence();
    }
    __syncthreads();
}

// ---------------- split-bf16 big GEMM (legacy mma m16n8k16) ------------------
// C[M, N] = (Ahi+Alo)[M,512] @ (Bhi+Blo)[N,512]^T (+bias[n] if bias != null).
// 3-term split: Ahi*Bhi + Ahi*Blo + Alo*Bhi  (lo*lo dropped, ~2^-17 rel).
// Tile 128x128, BK=32 bf16, double-buffered cp.async. M must be mult of 128.
// smem: 2 stages x 4 sub-tiles (Ahi,Alo,Bhi,Blo) x [128 rows x 80 bytes].
#define BT_ROW   80                     // 32 bf16 padded to 40 (word stride 20)
#define BT_TILE  (128 * BT_ROW)         // 10240 B
#define BT_STAGE (4 * BT_TILE)          // 40960 B
#define BT_SMEM  (2 * BT_STAGE)         // 81920 B

__global__ void __launch_bounds__(256)
gemm_bf16(const __nv_bfloat16* __restrict__ Ahi, const __nv_bfloat16* __restrict__ Alo,
          const __nv_bfloat16* __restrict__ Bhi, const __nv_bfloat16* __restrict__ Blo,
          float* __restrict__ C, int M, int N, int K,
          const float* __restrict__ bias) {
    extern __shared__ char smem[];
    const int tid = threadIdx.x;
    const int ln  = tid & 31;
    const int w   = tid >> 5;
    const int wm  = w & 1;    // 2 row groups of 64
    const int wn  = w >> 1;   // 4 col groups of 32
    const int bm0 = blockIdx.y * 128;
    const int bn0 = blockIdx.x * 128;
    unsigned sb = (unsigned)__cvta_generic_to_shared(smem);

    float acc[4][4][4];
    #pragma unroll
    for (int a = 0; a < 4; a++)
        #pragma unroll
        for (int b = 0; b < 4; b++)
            #pragma unroll
            for (int c = 0; c < 4; c++) acc[a][b][c] = 0.0f;

    const int nk = K >> 5;   // 32 bf16 per chunk

    // fill one stage: 4 tiles x 128 rows x 2 halves (16B each); 8 cp per thread
    #define BT_FILL(stage, k0)                                                   \
    do {                                                                         \
        unsigned base = sb + (stage) * BT_STAGE;                                 \
        _Pragma("unroll")                                                        \
        for (int half = 0; half < 2; half++) {                                   \
            int rem = half * 256 + tid;                                          \
            int r = rem >> 2, q = rem & 3;                                       \
            int kq = (k0) + q * 8;                                               \
            unsigned doff = r * BT_ROW + q * 16;                                 \
            size_t gA = (size_t)(bm0 + r) * 512 + kq;                            \
            cpA(base + doff,               Ahi + gA);                            \
            cpA(base + BT_TILE + doff,     Alo + gA);                            \
            int gr = bn0 + r;                                                    \
            bool ok = gr < N;                                                    \
            size_t gB = (size_t)gr * 512 + kq;                                   \
            cpAz(base + 2 * BT_TILE + doff, Bhi + gB, ok);                       \
            cpAz(base + 3 * BT_TILE + doff, Blo + gB, ok);                       \
        }                                                                        \
    } while (0)

    BT_FILL(0, 0);
    CP_COMMIT;

    for (int k0 = 0; k0 < nk; k0++) {
        if (k0 + 1 < nk) {
            BT_FILL((k0 + 1) & 1, (k0 + 1) * 32);
            CP_COMMIT; CP_WAIT1;
        } else {
            CP_WAIT0;
        }
        __syncthreads();

        const char* st = smem + (k0 & 1) * BT_STAGE;
        const int g = ln >> 2;
        #pragma unroll
        for (int kk = 0; kk < 2; kk++) {
            const int cb = kk * 16 + 2 * (ln & 3);   // even bf16 col in [0,32)
            unsigned ah[4][4], bh[4][2], bl[4][2];
            #pragma unroll
            for (int mt = 0; mt < 4; mt++) {
                const char* p = st + ((wm * 64 + mt * 16 + g) * BT_ROW) + cb * 2;
                ah[mt][0] = *(const unsigned*)(p);
                ah[mt][1] = *(const unsigned*)(p + 8 * BT_ROW);
                ah[mt][2] = *(const unsigned*)(p + 16);
                ah[mt][3] = *(const unsigned*)(p + 8 * BT_ROW + 16);
            }
            #pragma unroll
            for (int nt = 0; nt < 4; nt++) {
                const char* p = st + 2 * BT_TILE + ((wn * 32 + nt * 8 + g) * BT_ROW) + cb * 2;
                bh[nt][0] = *(const unsigned*)(p);
                bh[nt][1] = *(const unsigned*)(p + 16);
                bl[nt][0] = *(const unsigned*)(p + BT_TILE);
                bl[nt][1] = *(const unsigned*)(p + BT_TILE + 16);
            }
            // term0: Ahi*Bhi, term1: Ahi*Blo
            #pragma unroll
            for (int nt = 0; nt < 4; nt++)
                #pragma unroll
                for (int mt = 0; mt < 4; mt++) {
                    MMA_BF16(acc[mt][nt][0], acc[mt][nt][1], acc[mt][nt][2], acc[mt][nt][3],
                             ah[mt][0], ah[mt][1], ah[mt][2], ah[mt][3],
                             bh[nt][0], bh[nt][1]);
                    MMA_BF16(acc[mt][nt][0], acc[mt][nt][1], acc[mt][nt][2], acc[mt][nt][3],
                             ah[mt][0], ah[mt][1], ah[mt][2], ah[mt][3],
                             bl[nt][0], bl[nt][1]);
                }
            // term2: Alo*Bhi
            unsigned al[4][4];
            #pragma unroll
            for (int mt = 0; mt < 4; mt++) {
                const char* p = st + BT_TILE + ((wm * 64 + mt * 16 + g) * BT_ROW) + cb * 2;
                al[mt][0] = *(const unsigned*)(p);
                al[mt][1] = *(const unsigned*)(p + 8 * BT_ROW);
                al[mt][2] = *(const unsigned*)(p + 16);
                al[mt][3] = *(const unsigned*)(p + 8 * BT_ROW + 16);
            }
            #pragma unroll
            for (int nt = 0; nt < 4; nt++)
                #pragma unroll
                for (int mt = 0; mt < 4; mt++)
                    MMA_BF16(acc[mt][nt][0], acc[mt][nt][1], acc[mt][nt][2], acc[mt][nt][3],
                             al[mt][0], al[mt][1], al[mt][2], al[mt][3],
                             bh[nt][0], bh[nt][1]);
        }
        __syncthreads();
    }

    #pragma unroll
    for (int mt = 0; mt < 4; mt++)
        #pragma unroll
        for (int nt = 0; nt < 4; nt++)
            #pragma unroll
            for (int half = 0; half < 2; half++) {
                int gm = bm0 + wm * 64 + mt * 16 + (ln >> 2) + half * 8;
                int gn = bn0 + wn * 32 + nt * 8 + (ln & 3) * 2;
                if (gm < M && gn < N) {
                    float v0 = acc[mt][nt][half * 2 + 0];
                    float v1 = acc[mt][nt][half * 2 + 1];
                    if (bias) { v0 += bias[gn]; v1 += bias[gn + 1]; }
                    *(float2*)(C + (size_t)gm * N + gn) = make_float2(v0, v1);
                }
            }
}

// ---------------- small GEMM with internal cvt (fc only; K=2048) -------------
template<int BM, int BN, int WN, int EPI>
__global__ void __launch_bounds__((BM / 32) * (BN / WN) * 32)
gemm_tf32(const float* __restrict__ A, const float* __restrict__ Bm,
          float* __restrict__ C, int M, int N, int K,
          const float* __restrict__ aux1) {
    constexpr int NWM   = BM / 32;
    constexpr int NWN   = BN / WN;
    constexpr int NT    = NWM * NWN * 32;
    constexpr int NTILE = WN / 8;

    __shared__ unsigned As[BM][36];
    __shared__ unsigned Bs[BN][36];

    const int tid = threadIdx.x;
    const int ln  = tid & 31;
    const int wid = tid >> 5;
    const int wm  = wid % NWM;
    const int wn  = wid / NWM;
    const int bm0 = blockIdx.y * BM;
    const int bn0 = blockIdx.x * BN;

    float acc[2][NTILE][4];
    #pragma unroll
    for (int a = 0; a < 2; a++)
        #pragma unroll
        for (int b = 0; b < NTILE; b++)
            #pragma unroll
            for (int c = 0; c < 4; c++) acc[a][b][c] = 0.0f;

    for (int k0 = 0; k0 < K; k0 += 32) {
        #pragma unroll
        for (int i = 0; i < (BM * 8) / NT; i++) {
            int idx = tid + i * NT;
            int r = idx >> 3, c4 = idx & 7;
            float4 v = make_float4(0.f, 0.f, 0.f, 0.f);
            int gr = bm0 + r;
            if (gr < M) v = *(const float4*)(A + (size_t)gr * K + k0 + c4 * 4);
            As[r][c4 * 4 + 0] = f2tf32(v.x);
            As[r][c4 * 4 + 1] = f2tf32(v.y);
            As[r][c4 * 4 + 2] = f2tf32(v.z);
            As[r][c4 * 4 + 3] = f2tf32(v.w);
        }
        #pragma unroll
        for (int i = 0; i < (BN * 8) / NT; i++) {
            int idx = tid + i * NT;
            int r = idx >> 3, c4 = idx & 7;
            float4 v = make_float4(0.f, 0.f, 0.f, 0.f);
            int gr = bn0 + r;
            if (gr < N) v = *(const float4*)(Bm + (size_t)gr * K + k0 + c4 * 4);
            Bs[r][c4 * 4 + 0] = f2tf32(v.x);
            Bs[r][c4 * 4 + 1] = f2tf32(v.y);
            Bs[r][c4 * 4 + 2] = f2tf32(v.z);
            Bs[r][c4 * 4 + 3] = f2tf32(v.w);
        }
        __syncthreads();

        #pragma unroll
        for (int ks = 0; ks < 4; ks++) {
            const int kc = ks * 8;
            unsigned a[2][4];
            const int r0 = wm * 32;
            #pragma unroll
            for (int mt = 0; mt < 2; mt++) {
                const int R = r0 + mt * 16;
                a[mt][0] = As[R + (ln >> 2)][kc + (ln & 3)];
                a[mt][1] = As[R + (ln >> 2) + 8][kc + (ln & 3)];
                a[mt][2] = As[R + (ln >> 2)][kc + (ln & 3) + 4];
                a[mt][3] = As[R + (ln >> 2) + 8][kc + (ln & 3) + 4];
            }
            #pragma unroll
            for (int nt = 0; nt < NTILE; nt++) {
                const int Cb = wn * WN + nt * 8;
                unsigned b0 = Bs[Cb + (ln >> 2)][kc + (ln & 3)];
                unsigned b1 = Bs[Cb + (ln >> 2)][kc + (ln & 3) + 4];
                #pragma unroll
                for (int mt = 0; mt < 2; mt++) {
                    MMA_TF32(acc[mt][nt][0], acc[mt][nt][1], acc[mt][nt][2], acc[mt][nt][3],
                             a[mt][0], a[mt][1], a[mt][2], a[mt][3], b0, b1);
                }
            }
        }
        __syncthreads();
    }

    #pragma unroll
    for (int mt = 0; mt < 2; mt++)
        #pragma unroll
        for (int nt = 0; nt < NTILE; nt++)
            #pragma unroll
            for (int half = 0; half < 2; half++) {
                int gm = bm0 + wm * 32 + mt * 16 + (ln >> 2) + half * 8;
                int gn = bn0 + wn * WN + nt * 8 + (ln & 3) * 2;
                if (gm < M && gn < N) {
                    float v0 = acc[mt][nt][half * 2 + 0];
                    float v1 = acc[mt][nt][half * 2 + 1];
                    if (EPI == 1) { v0 += aux1[gn]; v1 += aux1[gn + 1]; }
                    *(float2*)(C + (size_t)gm * N + gn) = make_float2(v0, v1);
                }
            }
}

// ---------------- persistent recurrence kernel --------------------------------
#define STG_STRIDE 132
#define STG_BUF    (128 * STG_STRIDE)
__device__ __forceinline__ void stage128(float* dst, const float* src, int k0, int tid) {
    #pragma unroll
    for (int i = 0; i < 16; i++) {
        int idx = tid + i * 256;            // [0, 4096)
        int r = idx >> 5, c4 = idx & 31;    // 128 rows x 32 float4
        cp16(dst + r * STG_STRIDE + c4 * 4, src + (size_t)r * 512 + k0 + c4 * 4);
    }
}

__global__ void __launch_bounds__(256, 1)
recurrent_kernel(const float* __restrict__ bhh, float* __restrict__ out_hid) {
    extern __shared__ float sm[];
    float* Wa  = sm;                          // 16 x 516
    float* M2C = sm + 16 * 516;               // 24 x 516
    float* stg = sm + 16 * 516 + 24 * 516;    // 2 x 128 x 132

    const int bi  = blockIdx.x;
    const int tid = threadIdx.x;
    const int ln  = tid & 31;
    const int w   = tid >> 5;

    for (int i = tid; i < 16 * 512; i += 256) {
        int r = i >> 9, c = i & 511;
        Wa[r * 516 + c] = g_WpH[(size_t)(16 * bi + r) * 512 + c];
    }
    if (bi < 64) {
        for (int i = tid; i < 24 * 512; i += 256) {
            int r = i >> 9, c = i & 511;
            int g = r >> 3, i2 = r & 7;
            M2C[r * 516 + c] = g_M2[(size_t)(g * 512 + 8 * bi + i2) * 512 + c];
        }
    }
    __syncthreads();

    for (int t = 0; t < TT; t++) {
        const float* Pt = g_P + (size_t)t * BB * 2048;

        // ===== phase A: S = hR @ WpH^T (+Pt / +bhh) =====
        {
            float acc[2][4] = {{0.f,0.f,0.f,0.f},{0.f,0.f,0.f,0.f}};
            stage128(stg, g_hR, 0, tid); CP_COMMIT;
            for (int kc = 0; kc < 4; kc++) {
                if (kc < 3) {
                    stage128(stg + ((kc + 1) & 1) * STG_BUF, g_hR, (kc + 1) * 128, tid);
                    CP_COMMIT; CP_WAIT1;
                } else CP_WAIT0;
                __syncthreads();
                const float* hs = stg + (kc & 1) * STG_BUF;
                #pragma unroll
                for (int ks = 0; ks < 16; ks++) {
                    int ab = (16 * w + (ln >> 2)) * STG_STRIDE + ks * 8 + (ln & 3);
                    unsigned a0 = __float_as_uint(hs[ab]);
                    unsigned a1 = __float_as_uint(hs[ab + 8 * STG_STRIDE]);
                    unsigned a2 = __float_as_uint(hs[ab + 4]);
                    unsigned a3 = __float_as_uint(hs[ab + 8 * STG_STRIDE + 4]);
                    #pragma unroll
                    for (int nt = 0; nt < 2; nt++) {
                        int bb = (nt * 8 + (ln >> 2)) * 516 + kc * 128 + ks * 8 + (ln & 3);
                        unsigned b0 = __float_as_uint(Wa[bb]);
                        unsigned b1 = __float_as_uint(Wa[bb + 4]);
                        MMA_TF32(acc[nt][0], acc[nt][1], acc[nt][2], acc[nt][3],
                                 a0, a1, a2, a3, b0, b1);
                    }
                }
                __syncthreads();
            }
            #pragma unroll
            for (int nt = 0; nt < 2; nt++)
                #pragma unroll
                for (int half = 0; half < 2; half++) {
                    int gm = 16 * w + (ln >> 2) + half * 8;
                    int gc = 16 * bi + nt * 8 + (ln & 3) * 2;
                    float v0 = acc[nt][half * 2 + 0];
                    float v1 = acc[nt][half * 2 + 1];
                    if (bi < 32) {
                        v0 += Pt[(size_t)gm * 2048 + gc];
                        v1 += Pt[(size_t)gm * 2048 + gc + 1];
                    } else {
                        v0 += bhh[gc - 512];
                        v1 += bhh[gc - 511];
                    }
                    *(float2*)(g_S + (size_t)gm * 2048 + gc) = make_float2(v0, v1);
                }
        }
        grid_bar();

        // ===== phase B: softmax + applied (row bi) =====
        {
            float2 x = *(const float2*)(g_S + (size_t)bi * 2048 + tid * 2);
            float m = block_reduce_max(fmaxf(x.x, x.y));
            float e0 = expf(x.x - m), e1 = expf(x.y - m);
            float s = block_reduce_sum(e0 + e1);
            float inv = 1.0f / s;
            float2 fv = *(const float2*)(g_feats + (size_t)bi * 512 + tid * 2);
            *(float2*)(g_applied + (size_t)bi * 512 + tid * 2) =
                make_float2(rtf(fv.x * e0 * inv), rtf(fv.y * e1 * inv));
        }
        grid_bar();

        // ===== phase C: gx + GRU gates (blocks 0..63) =====
        if (bi < 64) {
            float acc[3][4];
            #pragma unroll
            for (int a = 0; a < 3; a++)
                #pragma unroll
                for (int c = 0; c < 4; c++) acc[a][c] = 0.0f;

            stage128(stg, g_applied, 0, tid); CP_COMMIT;
            for (int kc = 0; kc < 4; kc++) {
                if (kc < 3) {
                    stage128(stg + ((kc + 1) & 1) * STG_BUF, g_applied, (kc + 1) * 128, tid);
                    CP_COMMIT; CP_WAIT1;
                } else CP_WAIT0;
                __syncthreads();
                const float* ap = stg + (kc & 1) * STG_BUF;
                #pragma unroll
                for (int ks = 0; ks < 16; ks++) {
                    int ab = (16 * w + (ln >> 2)) * STG_STRIDE + ks * 8 + (ln & 3);
                    unsigned a0 = __float_as_uint(ap[ab]);
                    unsigned a1 = __float_as_uint(ap[ab + 8 * STG_STRIDE]);
                    unsigned a2 = __float_as_uint(ap[ab + 4]);
                    unsigned a3 = __float_as_uint(ap[ab + 8 * STG_STRIDE + 4]);
                    #pragma unroll
                    for (int nt = 0; nt < 3; nt++) {
                        int bb = (nt * 8 + (ln >> 2)) * 516 + kc * 128 + ks * 8 + (ln & 3);
                        unsigned b0 = __float_as_uint(M2C[bb]);
                        unsigned b1 = __float_as_uint(M2C[bb + 4]);
                        MMA_TF32(acc[nt][0], acc[nt][1], acc[nt][2], acc[nt][3],
                                 a0, a1, a2, a3, b0, b1);
                    }
                }
                __syncthreads();
            }
            #pragma unroll
            for (int half = 0; half < 2; half++) {
                int b = 16 * w + (ln >> 2) + half * 8;
                #pragma unroll
                for (int q = 0; q < 2; q++) {
                    int jj = (ln & 3) * 2 + q;
                    int j  = 8 * bi + jj;
                    float xr = acc[0][half * 2 + q] + Pt[(size_t)b * 2048 + 512  + j];
                    float xz = acc[1][half * 2 + q] + Pt[(size_t)b * 2048 + 1024 + j];
                    float xn = acc[2][half * 2 + q] + Pt[(size_t)b * 2048 + 1536 + j];
                    float hr = g_S[(size_t)b * 2048 + 512  + j];
                    float hz = g_S[(size_t)b * 2048 + 1024 + j];
                    float hn = g_S[(size_t)b * 2048 + 1536 + j];
                    float r = 1.0f / (1.0f + expf(-(xr + hr)));
                    float z = 1.0f / (1.0f + expf(-(xz + hz)));
                    float n = tanhf(xn + r * hn);
                    float hp = g_h[(size_t)b * 512 + j];
                    float hv = (1.0f - z) * n + z * hp;
                    size_t hsrow = ((size_t)t * 128 + b) * 512 + j;
                    g_h[(size_t)b * 512 + j]  = hv;        // full precision
                    g_hR[(size_t)b * 512 + j] = rtf(hv);   // tf32 for next step
                    split2(hv, &g_hshi[hsrow], &g_hslo[hsrow]);  // bf16 split: final GEMM
                    out_hid[((size_t)b * 64 + t) * 512 + j] = hv;
                }
            }
        }
        grid_bar();
    }
}

// ---------------- small kernels ----------------------------------------------
__global__ void bn_kernel(const float* __restrict__ f, const float* __restrict__ gamma,
                          const float* __restrict__ beta) {
    int j = blockIdx.x;
    int b = threadIdx.x;
    float x = f[b * EE + j];
    float s  = block_reduce_sum(x);
    float sq = block_reduce_sum(x * x);
    float mu  = s * (1.0f / BB);
    float var = sq * (1.0f / BB) - mu * mu;
    float y = gamma[j] * (x - mu) * rsqrtf(var + 1e-5f) + beta[j];
    g_feats[b * EE + j] = y;
    split2(y, &g_Xhi[b * EE + j], &g_Xlo[b * EE + j]);   // t = 0 row
}

__global__ void buildX_kernel(const int* __restrict__ captions,
                              const float* __restrict__ embW) {
    int b = blockIdx.x;
    int t = blockIdx.y + 1;
    int tid = threadIdx.x;
    int tok = captions[b * TT + (t - 1)];
    float4 v = *(const float4*)(embW + (size_t)tok * EE + tid * 4);
    size_t row = ((size_t)t * BB + b) * EE + tid * 4;
    split2(v.x, &g_Xhi[row + 0], &g_Xlo[row + 0]);
    split2(v.y, &g_Xhi[row + 1], &g_Xlo[row + 1]);
    split2(v.z, &g_Xhi[row + 2], &g_Xlo[row + 2]);
    split2(v.w, &g_Xhi[row + 3], &g_Xlo[row + 3]);
}

__global__ void conv_combWT(const float* __restrict__ comb_W) {
    int idx = blockIdx.x * blockDim.x + threadIdx.x;
    if (idx < 1024 * 512) {
        int n = idx >> 9, i = idx & 511;
        split2(comb_W[(size_t)i * 1024 + n], &g_combWThi[idx], &g_combWTlo[idx]);
    }
}

__global__ void conv_Wih(const float* __restrict__ Wih) {
    int idx = blockIdx.x * blockDim.x + threadIdx.x;
    if (idx < G3 * 512) split2(Wih[idx], &g_Wihhi[idx], &g_Wihlo[idx]);
}

__global__ void conv_outW(const float* __restrict__ outW) {
    int idx = blockIdx.x * blockDim.x + threadIdx.x;
    if (idx < VV * 512 / 4) {
        float4 v = ((const float4*)outW)[idx];
        int b = idx * 4;
        split2(v.x, &g_outWhi[b + 0], &g_outWlo[b + 0]);
        split2(v.y, &g_outWhi[b + 1], &g_outWlo[b + 1]);
        split2(v.z, &g_outWhi[b + 2], &g_outWlo[b + 2]);
        split2(v.w, &g_outWhi[b + 3], &g_outWlo[b + 3]);
    }
}

__global__ void biasg_kernel(const float* __restrict__ Wih,
                             const float* __restrict__ comb_b,
                             const float* __restrict__ bih) {
    int g = blockIdx.x;
    int tid = threadIdx.x;
    float s = 0.0f;
    for (int i = tid; i < 512; i += 128) s += Wih[(size_t)g * 512 + i] * comb_b[i];
    s = block_reduce_sum(s);
    if (tid == 0) g_bias0[512 + g] = s + bih[g];
}

__global__ void pack_kernel(const float* __restrict__ attn_W,
                            const float* __restrict__ gru_Whh,
                            const float* __restrict__ attn_b) {
    for (int idx = blockIdx.x * blockDim.x + threadIdx.x; idx < 2048 * 512;
         idx += gridDim.x * blockDim.x) {
        int j = idx >> 9, k = idx & 511;
        float wx = (j < 512) ? attn_W[(size_t)j * 1024 + k]
                             : g_Mmat[(size_t)(j - 512) * 1024 + k];
        split2(wx, &g_WpXhi[idx], &g_WpXlo[idx]);
        g_WpH[idx] = rtf((j < 512) ? attn_W[(size_t)j * 1024 + 512 + k]
                                   : gru_Whh[(size_t)(j - 512) * 512 + k]);
        if (j < G3) g_M2[idx] = rtf(g_Mmat[(size_t)j * 1024 + 512 + k]);
        if (idx < 512) g_bias0[idx] = attn_b[idx];
    }
}

__global__ void copyh_kernel(const float* __restrict__ src) {
    int i = blockIdx.x * blockDim.x + threadIdx.x;
    if (i < BB * HH) {
        float v = src[i];
        g_h[i]  = v;
        g_hR[i] = rtf(v);
    }
}

// fused logsumexp + apply
__global__ void lse_apply(float* __restrict__ logits) {
    size_t base = (size_t)blockIdx.x * VV;
    float4* rv = (float4*)(logits + base);
    int tid = threadIdx.x;
    float m = -3.0e38f;
    for (int i = tid; i < VV / 4; i += 256) {
        float4 v = rv[i];
        m = fmaxf(m, fmaxf(fmaxf(v.x, v.y), fmaxf(v.z, v.w)));
    }
    m = block_reduce_max(m);
    float s = 0.0f;
    for (int i = tid; i < VV / 4; i += 256) {
        float4 v = rv[i];
        s += expf(v.x - m) + expf(v.y - m) + expf(v.z - m) + expf(v.w - m);
    }
    s = block_reduce_sum(s);
    float lse = m + logf(s);
    for (int i = tid; i < VV / 4; i += 256) {
        float4 v = rv[i];
        v.x -= lse; v.y -= lse; v.z -= lse; v.w -= lse;
        rv[i] = v;
    }
}

// ---------------- host driver -------------------------------------------------
template<typename Tp>
static void* symaddr(Tp& ref) {
    void* p = nullptr;
    cudaGetSymbolAddress(&p, ref);
    return p;
}

extern "C" void kernel_launch(void* const* d_in, const int* in_sizes, int n_in,
                              void* d_out, int out_size) {
    const float* features = (const float*)d_in[0];
    const int*   captions = (const int*)d_in[1];
    const float* h0       = (const float*)d_in[2];
    const float* embed_W  = (const float*)d_in[4];
    const float* fc_W     = (const float*)d_in[5];
    const float* fc_b     = (const float*)d_in[6];
    const float* bn_gamma = (const float*)d_in[7];
    const float* bn_beta  = (const float*)d_in[8];
    const float* attn_W   = (const float*)d_in[9];
    const float* attn_b   = (const float*)d_in[10];
    const float* comb_W   = (const float*)d_in[11];
    const float* comb_b   = (const float*)d_in[12];
    const float* gru_Wih  = (const float*)d_in[13];
    const float* gru_Whh  = (const float*)d_in[14];
    const float* gru_bih  = (const float*)d_in[15];
    const float* gru_bhh  = (const float*)d_in[16];
    const float* out_W    = (const float*)d_in[17];
    const float* out_b    = (const float*)d_in[18];

    float* out_logp = (float*)d_out;
    float* out_hid  = out_logp + (size_t)TT * BB * VV;

    float* p_fpre  = (float*)symaddr(g_fpre);
    float* p_P     = (float*)symaddr(g_P);
    float* p_Mmat  = (float*)symaddr(g_Mmat);
    float* p_bias0 = (float*)symaddr(g_bias0);
    __nv_bfloat16* p_cwh = (__nv_bfloat16*)symaddr(g_combWThi);
    __nv_bfloat16* p_cwl = (__nv_bfloat16*)symaddr(g_combWTlo);
    __nv_bfloat16* p_wih = (__nv_bfloat16*)symaddr(g_Wihhi);
    __nv_bfloat16* p_wil = (__nv_bfloat16*)symaddr(g_Wihlo);
    __nv_bfloat16* p_xh  = (__nv_bfloat16*)symaddr(g_Xhi);
    __nv_bfloat16* p_xl  = (__nv_bfloat16*)symaddr(g_Xlo);
    __nv_bfloat16* p_pxh = (__nv_bfloat16*)symaddr(g_WpXhi);
    __nv_bfloat16* p_pxl = (__nv_bfloat16*)symaddr(g_WpXlo);
    __nv_bfloat16* p_owh = (__nv_bfloat16*)symaddr(g_outWhi);
    __nv_bfloat16* p_owl = (__nv_bfloat16*)symaddr(g_outWlo);
    __nv_bfloat16* p_hsh = (__nv_bfloat16*)symaddr(g_hshi);
    __nv_bfloat16* p_hsl = (__nv_bfloat16*)symaddr(g_hslo);

    const int RK_SMEM = (16 * 516 + 24 * 516 + 2 * STG_BUF) * 4;
    cudaFuncSetAttribute(recurrent_kernel, cudaFuncAttributeMaxDynamicSharedMemorySize, RK_SMEM);
    cudaFuncSetAttribute(gemm_bf16, cudaFuncAttributeMaxDynamicSharedMemorySize, BT_SMEM);

    // 0. comb_W^T -> bf16 split
    conv_combWT<<<(1024 * 512 + 255) / 256, 256>>>(comb_W);
    // 1. gru_Wih -> bf16 split
    conv_Wih<<<(G3 * 512 + 255) / 256, 256>>>(gru_Wih);
    // 2. fc (legacy tf32 path, K=2048)
    gemm_tf32<64, 64, 32, 1><<<dim3(8, 2), 128>>>(
        features, fc_W, p_fpre, BB, EE, FIN, fc_b);
    // 3. Mmat = Wih @ comb_W via split-bf16  <-- PROFILED SLOT
    gemm_bf16<<<dim3(8, 12), 256, BT_SMEM>>>(
        p_wih, p_wil, p_cwh, p_cwl, p_Mmat, G3, 1024, 512, nullptr);
    // 4. BatchNorm -> feats + X[t=0] splits
    bn_kernel<<<EE, BB>>>(p_fpre, bn_gamma, bn_beta);
    // 5. X[t>=1] splits
    buildX_kernel<<<dim3(BB, TT - 1), 128>>>(captions, embed_W);
    // 6. out_W -> bf16 split
    conv_outW<<<(VV * 512 / 4 + 255) / 256, 256>>>(out_W);
    // 7. gh bias (fp32)
    biasg_kernel<<<G3, 128>>>(gru_Wih, comb_b, gru_bih);
    // 8. pack (WpX splits, WpH/M2 tf32, bias0)
    pack_kernel<<<2048, 512>>>(attn_W, gru_Whh, attn_b);
    // 9. P_all = X @ WpX^T + bias0 via split-bf16
    gemm_bf16<<<dim3(16, 64), 256, BT_SMEM>>>(
        p_xh, p_xl, p_pxh, p_pxl, p_P, TT * BB, 2048, 512, p_bias0);
    // 10. h = h0
    copyh_kernel<<<(BB * HH + 255) / 256, 256>>>(h0);
    // 11. persistent recurrence
    recurrent_kernel<<<NBLK, 256, RK_SMEM>>>(gru_bhh, out_hid);
    // 12. logits = hs @ out_W^T + out_b via split-bf16
    gemm_bf16<<<dim3((VV + 127) / 128, (TT * BB) / 128), 256, BT_SMEM>>>(
        p_hsh, p_hsl, p_owh, p_owl, out_logp, TT * BB, VV, 512, out_b);
    // 13. fused log_softmax
    lse_apply<<<TT * BB, 256>>>(out_logp);
}

// round 15
// speedup vs baseline: 1.1664x; 1.1664x over previous
#include <cuda_runtime.h>
#include <cuda_fp16.h>
#include <math.h>

// Problem constants
#define BB   128
#define TT   64
#define EE   512
#define HH   512
#define VV   10000
#define FIN  2048
#define G3   1536   // 3*H
#define NBLK 128    // persistent kernel grid size

// ---------------- scratch (device globals; no allocations allowed) ----------
__device__ float g_X[TT * BB * EE];        // x_seq (tf32-rounded), time-major
__device__ float g_P[TT * BB * 2048];      // precomputed x-parts [T,B,2048]
__device__ float g_fpre[BB * EE];
__device__ float g_feats[BB * EE];         // full precision
__device__ float g_combWT[1024 * 512];     // comb_W^T, tf32-rounded
__device__ float g_WihR[G3 * 512];         // gru_Wih, tf32-rounded
__device__ float g_Mmat[G3 * 1024];        // gru_Wih @ comb_W (fp32 result)
__device__ float g_WpX[2048 * 512];        // [attn_Wx ; M1], tf32-rounded
__device__ float g_WpH[2048 * 512];        // [attn_Wh ; gru_Whh], tf32-rounded
__device__ float g_M2[G3 * 512];           // M[:,512:], tf32-rounded
__device__ float g_bias0[2048];            // [attn_b ; gru_Wih@comb_b + gru_bih]
__device__ float g_S[BB * 2048];           // per-step: [attn scores ; gh]
__device__ float g_applied[BB * EE];       // tf32-rounded
__device__ float g_h[BB * HH];             // hidden state, full precision
__device__ float g_hR[BB * HH];            // hidden state, tf32-rounded
__device__ __half g_hsH[TT * BB * HH];     // time-major hiddens, fp16 (final GEMM A)
__device__ __half g_outWH[VV * 512];       // out_W, fp16 (final GEMM B)
__device__ unsigned g_bar_count = 0;
__device__ unsigned g_bar_gen   = 0;

// ---------------- helpers ----------------------------------------------------
__device__ __forceinline__ unsigned f2tf32(float x) {
    unsigned r;
    asm("cvt.rna.tf32.f32 %0, %1;" : "=r"(r) : "f"(x));
    return r;
}
__device__ __forceinline__ float rtf(float x) {   // RN-round to tf32, as float
    return __uint_as_float(f2tf32(x));
}
__device__ __forceinline__ float4 rtf4(float4 v) {
    return make_float4(rtf(v.x), rtf(v.y), rtf(v.z), rtf(v.w));
}

__device__ __forceinline__ float block_reduce_sum(float v) {
    __shared__ float buf[32];
    int tid = threadIdx.x, lane = tid & 31, wid = tid >> 5;
    int nw = (blockDim.x + 31) >> 5;
    #pragma unroll
    for (int o = 16; o > 0; o >>= 1) v += __shfl_xor_sync(0xFFFFFFFFu, v, o);
    if (lane == 0) buf[wid] = v;
    __syncthreads();
    float r = (tid < nw) ? buf[tid] : 0.0f;
    if (wid == 0) {
        #pragma unroll
        for (int o = 16; o > 0; o >>= 1) r += __shfl_xor_sync(0xFFFFFFFFu, r, o);
        if (lane == 0) buf[0] = r;
    }
    __syncthreads();
    r = buf[0];
    __syncthreads();
    return r;
}

__device__ __forceinline__ float block_reduce_max(float v) {
    __shared__ float buf[32];
    int tid = threadIdx.x, lane = tid & 31, wid = tid >> 5;
    int nw = (blockDim.x + 31) >> 5;
    #pragma unroll
    for (int o = 16; o > 0; o >>= 1) v = fmaxf(v, __shfl_xor_sync(0xFFFFFFFFu, v, o));
    if (lane == 0) buf[wid] = v;
    __syncthreads();
    float r = (tid < nw) ? buf[tid] : -3.0e38f;
    if (wid == 0) {
        #pragma unroll
        for (int o = 16; o > 0; o >>= 1) r = fmaxf(r, __shfl_xor_sync(0xFFFFFFFFu, r, o));
        if (lane == 0) buf[0] = r;
    }
    __syncthreads();
    r = buf[0];
    __syncthreads();
    return r;
}

// cp.async helpers
__device__ __forceinline__ void cp16(float* dst, const float* src) {
    unsigned d = (unsigned)__cvta_generic_to_shared(dst);
    asm volatile("cp.async.cg.shared.global [%0], [%1], 16;" :: "r"(d), "l"(src));
}
__device__ __forceinline__ void cpA(unsigned dst_smem, const void* src) {
    asm volatile("cp.async.cg.shared.global [%0], [%1], 16;" :: "r"(dst_smem), "l"(src));
}
__device__ __forceinline__ void cpAz(unsigned dst_smem, const void* src, bool p) {
    int sz = p ? 16 : 0;
    asm volatile("cp.async.cg.shared.global [%0], [%1], 16, %2;" :: "r"(dst_smem), "l"(src), "r"(sz));
}
#define CP_COMMIT asm volatile("cp.async.commit_group;")
#define CP_WAIT1  asm volatile("cp.async.wait_group 1;")
#define CP_WAIT0  asm volatile("cp.async.wait_group 0;")

#define MMA_TF32(d0,d1,d2,d3,a0,a1,a2,a3,b0,b1)                          \
    asm volatile("mma.sync.aligned.m16n8k8.row.col.f32.tf32.tf32.f32 "   \
        "{%0,%1,%2,%3},{%4,%5,%6,%7},{%8,%9},{%0,%1,%2,%3};"             \
        : "+f"(d0), "+f"(d1), "+f"(d2), "+f"(d3)                         \
        : "r"(a0), "r"(a1), "r"(a2), "r"(a3), "r"(b0), "r"(b1))

#define MMA_FP16(d0,d1,d2,d3,a0,a1,a2,a3,b0,b1)                          \
    asm volatile("mma.sync.aligned.m16n8k16.row.col.f32.f16.f16.f32 "    \
        "{%0,%1,%2,%3},{%4,%5,%6,%7},{%8,%9},{%0,%1,%2,%3};"             \
        : "+f"(d0), "+f"(d1), "+f"(d2), "+f"(d3)                         \
        : "r"(a0), "r"(a1), "r"(a2), "r"(a3), "r"(b0), "r"(b1))

// Software grid barrier (all NBLK blocks co-resident: 1 CTA/SM, NBLK=128<=148)
// Tight spin (no nanosleep) — barrier release latency is on the critical path
// 192 times per recurrence.
__device__ __forceinline__ void grid_bar() {
    __syncthreads();
    if (threadIdx.x == 0) {
        __threadfence();
        unsigned target = *(volatile unsigned*)&g_bar_gen + 1u;
        unsigned old = atomicAdd(&g_bar_count, 1u);
        if (old == NBLK - 1) {
            g_bar_count = 0;
            __threadfence();
            atomicExch(&g_bar_gen, target);
        } else {
            while (*(volatile unsigned*)&g_bar_gen < target) {}
        }
        __threadfence();
    }
    __syncthreads();
}

// ---------------- fp16 GEMM for the final projection -------------------------
// C[M, N] = A[M,512](fp16) @ B[N,512](fp16)^T + bias[n].  f32 accumulate.
// Tile 128x128, BK=32, double-buffered cp.async. M mult of 128.
#define HF_ROW   80                     // 32 fp16 = 64 B padded to 80
#define HF_TILE  (128 * HF_ROW)         // 10240 B
#define HF_STAGE (2 * HF_TILE)          // A + B = 20480 B
#define HF_SMEM  (2 * HF_STAGE)         // 40960 B

__global__ void __launch_bounds__(256, 2)
gemm_fp16(const __half* __restrict__ A, const __half* __restrict__ Bm,
          float* __restrict__ C, int M, int N, int K,
          const float* __restrict__ bias) {
    extern __shared__ char smem[];
    const int tid = threadIdx.x;
    const int ln  = tid & 31;
    const int w   = tid >> 5;
    const int wm  = w & 1;    // 2 row groups of 64
    const int wn  = w >> 1;   // 4 col groups of 32
    const int bm0 = blockIdx.y * 128;
    const int bn0 = blockIdx.x * 128;
    unsigned sb = (unsigned)__cvta_generic_to_shared(smem);

    float acc[4][4][4];
    #pragma unroll
    for (int a = 0; a < 4; a++)
        #pragma unroll
        for (int b = 0; b < 4; b++)
            #pragma unroll
            for (int c = 0; c < 4; c++) acc[a][b][c] = 0.0f;

    const int nk = K >> 5;   // 32 fp16 per chunk

    #define HF_FILL(stage, k0)                                                   \
    do {                                                                         \
        unsigned base = sb + (stage) * HF_STAGE;                                 \
        _Pragma("unroll")                                                        \
        for (int half_i = 0; half_i < 2; half_i++) {                             \
            int rem = half_i * 256 + tid;                                        \
            int r = rem >> 2, q = rem & 3;                                       \
            int kq = (k0) + q * 8;                                               \
            unsigned doff = r * HF_ROW + q * 16;                                 \
            cpA(base + doff, A + (size_t)(bm0 + r) * 512 + kq);                  \
            int gr = bn0 + r;                                                    \
            cpAz(base + HF_TILE + doff, Bm + (size_t)gr * 512 + kq, gr < N);     \
        }                                                                        \
    } while (0)

    HF_FILL(0, 0);
    CP_COMMIT;

    for (int k0 = 0; k0 < nk; k0++) {
        if (k0 + 1 < nk) {
            HF_FILL((k0 + 1) & 1, (k0 + 1) * 32);
            CP_COMMIT; CP_WAIT1;
        } else {
            CP_WAIT0;
        }
        __syncthreads();

        const char* st = smem + (k0 & 1) * HF_STAGE;
        const int g = ln >> 2;
        #pragma unroll
        for (int kk = 0; kk < 2; kk++) {
            const int cb = kk * 16 + 2 * (ln & 3);   // fp16 col pair start in [0,32)
            unsigned a[4][4], b[4][2];
            #pragma unroll
            for (int mt = 0; mt < 4; mt++) {
                const char* p = st + ((wm * 64 + mt * 16 + g) * HF_ROW) + cb * 2;
                a[mt][0] = *(const unsigned*)(p);
                a[mt][1] = *(const unsigned*)(p + 8 * HF_ROW);
                a[mt][2] = *(const unsigned*)(p + 16);
                a[mt][3] = *(const unsigned*)(p + 8 * HF_ROW + 16);
            }
            #pragma unroll
            for (int nt = 0; nt < 4; nt++) {
                const char* p = st + HF_TILE + ((wn * 32 + nt * 8 + g) * HF_ROW) + cb * 2;
                b[nt][0] = *(const unsigned*)(p);
                b[nt][1] = *(const unsigned*)(p + 16);
            }
            #pragma unroll
            for (int nt = 0; nt < 4; nt++)
                #pragma unroll
                for (int mt = 0; mt < 4; mt++)
                    MMA_FP16(acc[mt][nt][0], acc[mt][nt][1], acc[mt][nt][2], acc[mt][nt][3],
                             a[mt][0], a[mt][1], a[mt][2], a[mt][3],
                             b[nt][0], b[nt][1]);
        }
        __syncthreads();
    }

    #pragma unroll
    for (int mt = 0; mt < 4; mt++)
        #pragma unroll
        for (int nt = 0; nt < 4; nt++)
            #pragma unroll
            for (int half_i = 0; half_i < 2; half_i++) {
                int gm = bm0 + wm * 64 + mt * 16 + (ln >> 2) + half_i * 8;
                int gn = bn0 + wn * 32 + nt * 8 + (ln & 3) * 2;
                if (gm < M && gn < N) {
                    float v0 = acc[mt][nt][half_i * 2 + 0] + bias[gn];
                    float v1 = acc[mt][nt][half_i * 2 + 1] + bias[gn + 1];
                    *(float2*)(C + (size_t)gm * N + gn) = make_float2(v0, v1);
                }
            }
}

// ---------------- tuned big GEMM: 128x128x32, 2-stage cp.async (tf32) --------
// Operands MUST be pre-rounded to tf32 (raw-bit feed is then exact).
template<int EPI>
__global__ void __launch_bounds__(256, 2)
gemm_big(const float* __restrict__ A, const float* __restrict__ Bm,
         float* __restrict__ C, int M, int N, int K,
         const float* __restrict__ bias) {
    extern __shared__ float smf[];
    float* As = smf;            // [2][128*36]
    float* Bs = smf + 2 * 4608; // [2][128*36]

    const int tid = threadIdx.x;
    const int ln  = tid & 31;
    const int w   = tid >> 5;
    const int wm  = w & 1;
    const int wn  = w >> 1;
    const int bm0 = blockIdx.y * 128;
    const int bn0 = blockIdx.x * 128;

    float acc[4][4][4];
    #pragma unroll
    for (int a = 0; a < 4; a++)
        #pragma unroll
        for (int b = 0; b < 4; b++)
            #pragma unroll
            for (int c = 0; c < 4; c++) acc[a][b][c] = 0.0f;

    const int nk = K >> 5;

    {
        #pragma unroll
        for (int i = 0; i < 4; i++) {
            int idx = tid + i * 256;
            int r = idx >> 3, c4 = idx & 7;
            cp16(As + r * 36 + c4 * 4, A + (size_t)(bm0 + r) * K + c4 * 4);
        }
        #pragma unroll
        for (int i = 0; i < 4; i++) {
            int idx = tid + i * 256;
            int r = idx >> 3, c4 = idx & 7;
            int gr = bn0 + r;
            cpAz((unsigned)__cvta_generic_to_shared(Bs + r * 36 + c4 * 4),
                 Bm + (size_t)gr * K + c4 * 4, gr < N);
        }
        CP_COMMIT;
    }

    for (int k0 = 0; k0 < nk; k0++) {
        if (k0 + 1 < nk) {
            int s = (k0 + 1) & 1;
            int kb = (k0 + 1) * 32;
            #pragma unroll
            for (int i = 0; i < 4; i++) {
                int idx = tid + i * 256;
                int r = idx >> 3, c4 = idx & 7;
                cp16(As + s * 4608 + r * 36 + c4 * 4,
                     A + (size_t)(bm0 + r) * K + kb + c4 * 4);
            }
            #pragma unroll
            for (int i = 0; i < 4; i++) {
                int idx = tid + i * 256;
                int r = idx >> 3, c4 = idx & 7;
                int gr = bn0 + r;
                cpAz((unsigned)__cvta_generic_to_shared(Bs + s * 4608 + r * 36 + c4 * 4),
                     Bm + (size_t)gr * K + kb + c4 * 4, gr < N);
            }
            CP_COMMIT;
            CP_WAIT1;
        } else {
            CP_WAIT0;
        }
        __syncthreads();

        const float* Ac = As + (k0 & 1) * 4608;
        const float* Bc = Bs + (k0 & 1) * 4608;
        #pragma unroll
        for (int ks = 0; ks < 4; ks++) {
            unsigned a[4][4];
            #pragma unroll
            for (int mt = 0; mt < 4; mt++) {
                int base = (wm * 64 + mt * 16 + (ln >> 2)) * 36 + ks * 8 + (ln & 3);
                a[mt][0] = __float_as_uint(Ac[base]);
                a[mt][1] = __float_as_uint(Ac[base + 8 * 36]);
                a[mt][2] = __float_as_uint(Ac[base + 4]);
                a[mt][3] = __float_as_uint(Ac[base + 8 * 36 + 4]);
            }
            #pragma unroll
            for (int nt = 0; nt < 4; nt++) {
                int bb = (wn * 32 + nt * 8 + (ln >> 2)) * 36 + ks * 8 + (ln & 3);
                unsigned b0 = __float_as_uint(Bc[bb]);
                unsigned b1 = __float_as_uint(Bc[bb + 4]);
                #pragma unroll
                for (int mt = 0; mt < 4; mt++) {
                    MMA_TF32(acc[mt][nt][0], acc[mt][nt][1], acc[mt][nt][2], acc[mt][nt][3],
                             a[mt][0], a[mt][1], a[mt][2], a[mt][3], b0, b1);
                }
            }
        }
        __syncthreads();
    }

    #pragma unroll
    for (int mt = 0; mt < 4; mt++)
        #pragma unroll
        for (int nt = 0; nt < 4; nt++)
            #pragma unroll
            for (int half_i = 0; half_i < 2; half_i++) {
                int gm = bm0 + wm * 64 + mt * 16 + (ln >> 2) + half_i * 8;
                int gn = bn0 + wn * 32 + nt * 8 + (ln & 3) * 2;
                if (gm < M && gn < N) {
                    float v0 = acc[mt][nt][half_i * 2 + 0];
                    float v1 = acc[mt][nt][half_i * 2 + 1];
                    if (EPI == 1) { v0 += bias[gn]; v1 += bias[gn + 1]; }
                    *(float2*)(C + (size_t)gm * N + gn) = make_float2(v0, v1);
                }
            }
}

// ---------------- small GEMM with internal cvt (fc only; K=2048) -------------
template<int BM, int BN, int WN, int EPI>
__global__ void __launch_bounds__((BM / 32) * (BN / WN) * 32)
gemm_tf32(const float* __restrict__ A, const float* __restrict__ Bm,
          float* __restrict__ C, int M, int N, int K,
          const float* __restrict__ aux1) {
    constexpr int NWM   = BM / 32;
    constexpr int NWN   = BN / WN;
    constexpr int NT    = NWM * NWN * 32;
    constexpr int NTILE = WN / 8;

    __shared__ unsigned As[BM][36];
    __shared__ unsigned Bs[BN][36];

    const int tid = threadIdx.x;
    const int ln  = tid & 31;
    const int wid = tid >> 5;
    const int wm  = wid % NWM;
    const int wn  = wid / NWM;
    const int bm0 = blockIdx.y * BM;
    const int bn0 = blockIdx.x * BN;

    float acc[2][NTILE][4];
    #pragma unroll
    for (int a = 0; a < 2; a++)
        #pragma unroll
        for (int b = 0; b < NTILE; b++)
            #pragma unroll
            for (int c = 0; c < 4; c++) acc[a][b][c] = 0.0f;

    for (int k0 = 0; k0 < K; k0 += 32) {
        #pragma unroll
        for (int i = 0; i < (BM * 8) / NT; i++) {
            int idx = tid + i * NT;
            int r = idx >> 3, c4 = idx & 7;
            float4 v = make_float4(0.f, 0.f, 0.f, 0.f);
            int gr = bm0 + r;
            if (gr < M) v = *(const float4*)(A + (size_t)gr * K + k0 + c4 * 4);
            As[r][c4 * 4 + 0] = f2tf32(v.x);
            As[r][c4 * 4 + 1] = f2tf32(v.y);
            As[r][c4 * 4 + 2] = f2tf32(v.z);
            As[r][c4 * 4 + 3] = f2tf32(v.w);
        }
        #pragma unroll
        for (int i = 0; i < (BN * 8) / NT; i++) {
            int idx = tid + i * NT;
            int r = idx >> 3, c4 = idx & 7;
            float4 v = make_float4(0.f, 0.f, 0.f, 0.f);
            int gr = bn0 + r;
            if (gr < N) v = *(const float4*)(Bm + (size_t)gr * K + k0 + c4 * 4);
            Bs[r][c4 * 4 + 0] = f2tf32(v.x);
            Bs[r][c4 * 4 + 1] = f2tf32(v.y);
            Bs[r][c4 * 4 + 2] = f2tf32(v.z);
            Bs[r][c4 * 4 + 3] = f2tf32(v.w);
        }
        __syncthreads();

        #pragma unroll
        for (int ks = 0; ks < 4; ks++) {
            const int kc = ks * 8;
            unsigned a[2][4];
            const int r0 = wm * 32;
            #pragma unroll
            for (int mt = 0; mt < 2; mt++) {
                const int R = r0 + mt * 16;
                a[mt][0] = As[R + (ln >> 2)][kc + (ln & 3)];
                a[mt][1] = As[R + (ln >> 2) + 8][kc + (ln & 3)];
                a[mt][2] = As[R + (ln >> 2)][kc + (ln & 3) + 4];
                a[mt][3] = As[R + (ln >> 2) + 8][kc + (ln & 3) + 4];
            }
            #pragma unroll
            for (int nt = 0; nt < NTILE; nt++) {
                const int Cb = wn * WN + nt * 8;
                unsigned b0 = Bs[Cb + (ln >> 2)][kc + (ln & 3)];
                unsigned b1 = Bs[Cb + (ln >> 2)][kc + (ln & 3) + 4];
                #pragma unroll
                for (int mt = 0; mt < 2; mt++) {
                    MMA_TF32(acc[mt][nt][0], acc[mt][nt][1], acc[mt][nt][2], acc[mt][nt][3],
                             a[mt][0], a[mt][1], a[mt][2], a[mt][3], b0, b1);
                }
            }
        }
        __syncthreads();
    }

    #pragma unroll
    for (int mt = 0; mt < 2; mt++)
        #pragma unroll
        for (int nt = 0; nt < NTILE; nt++)
            #pragma unroll
            for (int half_i = 0; half_i < 2; half_i++) {
                int gm = bm0 + wm * 32 + mt * 16 + (ln >> 2) + half_i * 8;
                int gn = bn0 + wn * WN + nt * 8 + (ln & 3) * 2;
                if (gm < M && gn < N) {
                    float v0 = acc[mt][nt][half_i * 2 + 0];
                    float v1 = acc[mt][nt][half_i * 2 + 1];
                    if (EPI == 1) { v0 += aux1[gn]; v1 += aux1[gn + 1]; }
                    *(float2*)(C + (size_t)gm * N + gn) = make_float2(v0, v1);
                }
            }
}

// ---------------- persistent recurrence kernel --------------------------------
#define STG_STRIDE 132
#define STG_BUF    (128 * STG_STRIDE)
__device__ __forceinline__ void stage128(float* dst, const float* src, int k0, int tid) {
    #pragma unroll
    for (int i = 0; i < 16; i++) {
        int idx = tid + i * 256;            // [0, 4096)
        int r = idx >> 5, c4 = idx & 31;    // 128 rows x 32 float4
        cp16(dst + r * STG_STRIDE + c4 * 4, src + (size_t)r * 512 + k0 + c4 * 4);
    }
}

__global__ void __launch_bounds__(256, 1)
recurrent_kernel(const float* __restrict__ bhh, float* __restrict__ out_hid) {
    extern __shared__ float sm[];
    float* Wa  = sm;                          // 16 x 516
    float* M2C = sm + 16 * 516;               // 24 x 516
    float* stg = sm + 16 * 516 + 24 * 516;    // 2 x 128 x 132

    const int bi  = blockIdx.x;
    const int tid = threadIdx.x;
    const int ln  = tid & 31;
    const int w   = tid >> 5;

    for (int i = tid; i < 16 * 512; i += 256) {
        int r = i >> 9, c = i & 511;
        Wa[r * 516 + c] = g_WpH[(size_t)(16 * bi + r) * 512 + c];
    }
    if (bi < 64) {
        for (int i = tid; i < 24 * 512; i += 256) {
            int r = i >> 9, c = i & 511;
            int g = r >> 3, i2 = r & 7;
            M2C[r * 516 + c] = g_M2[(size_t)(g * 512 + 8 * bi + i2) * 512 + c];
        }
    }
    __syncthreads();

    for (int t = 0; t < TT; t++) {
        const float* Pt = g_P + (size_t)t * BB * 2048;

        // ===== phase A: S = hR @ WpH^T (+Pt / +bhh) =====
        {
            float acc[2][4] = {{0.f,0.f,0.f,0.f},{0.f,0.f,0.f,0.f}};
            stage128(stg, g_hR, 0, tid); CP_COMMIT;
            for (int kc = 0; kc < 4; kc++) {
                if (kc < 3) {
                    stage128(stg + ((kc + 1) & 1) * STG_BUF, g_hR, (kc + 1) * 128, tid);
                    CP_COMMIT; CP_WAIT1;
                } else CP_WAIT0;
                __syncthreads();
                const float* hs = stg + (kc & 1) * STG_BUF;
                #pragma unroll
                for (int ks = 0; ks < 16; ks++) {
                    int ab = (16 * w + (ln >> 2)) * STG_STRIDE + ks * 8 + (ln & 3);
                    unsigned a0 = __float_as_uint(hs[ab]);
                    unsigned a1 = __float_as_uint(hs[ab + 8 * STG_STRIDE]);
                    unsigned a2 = __float_as_uint(hs[ab + 4]);
                    unsigned a3 = __float_as_uint(hs[ab + 8 * STG_STRIDE + 4]);
                    #pragma unroll
                    for (int nt = 0; nt < 2; nt++) {
                        int bb = (nt * 8 + (ln >> 2)) * 516 + kc * 128 + ks * 8 + (ln & 3);
                        unsigned b0 = __float_as_uint(Wa[bb]);
                        unsigned b1 = __float_as_uint(Wa[bb + 4]);
                        MMA_TF32(acc[nt][0], acc[nt][1], acc[nt][2], acc[nt][3],
                                 a0, a1, a2, a3, b0, b1);
                    }
                }
                __syncthreads();
            }
            #pragma unroll
            for (int nt = 0; nt < 2; nt++)
                #pragma unroll
                for (int half_i = 0; half_i < 2; half_i++) {
                    int gm = 16 * w + (ln >> 2) + half_i * 8;
                    int gc = 16 * bi + nt * 8 + (ln & 3) * 2;
                    float v0 = acc[nt][half_i * 2 + 0];
                    float v1 = acc[nt][half_i * 2 + 1];
                    if (bi < 32) {
                        v0 += Pt[(size_t)gm * 2048 + gc];
                        v1 += Pt[(size_t)gm * 2048 + gc + 1];
                    } else {
                        v0 += bhh[gc - 512];
                        v1 += bhh[gc - 511];
                    }
                    *(float2*)(g_S + (size_t)gm * 2048 + gc) = make_float2(v0, v1);
                }
        }
        grid_bar();

        // ===== phase B: softmax + applied (row bi) =====
        {
            float2 x = *(const float2*)(g_S + (size_t)bi * 2048 + tid * 2);
            float m = block_reduce_max(fmaxf(x.x, x.y));
            float e0 = expf(x.x - m), e1 = expf(x.y - m);
            float s = block_reduce_sum(e0 + e1);
            float inv = 1.0f / s;
            float2 fv = *(const float2*)(g_feats + (size_t)bi * 512 + tid * 2);
            *(float2*)(g_applied + (size_t)bi * 512 + tid * 2) =
                make_float2(rtf(fv.x * e0 * inv), rtf(fv.y * e1 * inv));
        }
        grid_bar();

        // ===== phase C: gx + GRU gates (blocks 0..63) =====
        if (bi < 64) {
            float acc[3][4];
            #pragma unroll
            for (int a = 0; a < 3; a++)
                #pragma unroll
                for (int c = 0; c < 4; c++) acc[a][c] = 0.0f;

            stage128(stg, g_applied, 0, tid); CP_COMMIT;
            for (int kc = 0; kc < 4; kc++) {
                if (kc < 3) {
                    stage128(stg + ((kc + 1) & 1) * STG_BUF, g_applied, (kc + 1) * 128, tid);
                    CP_COMMIT; CP_WAIT1;
                } else CP_WAIT0;
                __syncthreads();
                const float* ap = stg + (kc & 1) * STG_BUF;
                #pragma unroll
                for (int ks = 0; ks < 16; ks++) {
                    int ab = (16 * w + (ln >> 2)) * STG_STRIDE + ks * 8 + (ln & 3);
                    unsigned a0 = __float_as_uint(ap[ab]);
                    unsigned a1 = __float_as_uint(ap[ab + 8 * STG_STRIDE]);
                    unsigned a2 = __float_as_uint(ap[ab + 4]);
                    unsigned a3 = __float_as_uint(ap[ab + 8 * STG_STRIDE + 4]);
                    #pragma unroll
                    for (int nt = 0; nt < 3; nt++) {
                        int bb = (nt * 8 + (ln >> 2)) * 516 + kc * 128 + ks * 8 + (ln & 3);
                        unsigned b0 = __float_as_uint(M2C[bb]);
                        unsigned b1 = __float_as_uint(M2C[bb + 4]);
                        MMA_TF32(acc[nt][0], acc[nt][1], acc[nt][2], acc[nt][3],
                                 a0, a1, a2, a3, b0, b1);
                    }
                }
                __syncthreads();
            }
            #pragma unroll
            for (int half_i = 0; half_i < 2; half_i++) {
                int b = 16 * w + (ln >> 2) + half_i * 8;
                #pragma unroll
                for (int q = 0; q < 2; q++) {
                    int jj = (ln & 3) * 2 + q;
                    int j  = 8 * bi + jj;
                    float xr = acc[0][half_i * 2 + q] + Pt[(size_t)b * 2048 + 512  + j];
                    float xz = acc[1][half_i * 2 + q] + Pt[(size_t)b * 2048 + 1024 + j];
                    float xn = acc[2][half_i * 2 + q] + Pt[(size_t)b * 2048 + 1536 + j];
                    float hr = g_S[(size_t)b * 2048 + 512  + j];
                    float hz = g_S[(size_t)b * 2048 + 1024 + j];
                    float hn = g_S[(size_t)b * 2048 + 1536 + j];
                    float r = 1.0f / (1.0f + expf(-(xr + hr)));
                    float z = 1.0f / (1.0f + expf(-(xz + hz)));
                    float n = tanhf(xn + r * hn);
                    float hp = g_h[(size_t)b * 512 + j];
                    float hv = (1.0f - z) * n + z * hp;
                    size_t hsrow = ((size_t)t * 128 + b) * 512 + j;
                    g_h[(size_t)b * 512 + j]  = hv;        // full precision
                    g_hR[(size_t)b * 512 + j] = rtf(hv);   // tf32 for next step
                    g_hsH[hsrow] = __float2half_rn(hv);    // fp16 for final GEMM
                    out_hid[((size_t)b * 64 + t) * 512 + j] = hv;
                }
            }
        }
        grid_bar();
    }
}

// ---------------- small kernels ----------------------------------------------
__global__ void bn_kernel(const float* __restrict__ f, const float* __restrict__ gamma,
                          const float* __restrict__ beta) {
    int j = blockIdx.x;
    int b = threadIdx.x;
    float x = f[b * EE + j];
    float s  = block_reduce_sum(x);
    float sq = block_reduce_sum(x * x);
    float mu  = s * (1.0f / BB);
    float var = sq * (1.0f / BB) - mu * mu;
    float y = gamma[j] * (x - mu) * rsqrtf(var + 1e-5f) + beta[j];
    g_feats[b * EE + j] = y;
    g_X[b * EE + j] = rtf(y);
}

__global__ void buildX_kernel(const int* __restrict__ captions,
                              const float* __restrict__ embW) {
    int b = blockIdx.x;
    int t = blockIdx.y + 1;
    int tid = threadIdx.x;
    int tok = captions[b * TT + (t - 1)];
    float4 v = *(const float4*)(embW + (size_t)tok * EE + tid * 4);
    *(float4*)(g_X + ((size_t)t * BB + b) * EE + tid * 4) = rtf4(v);
}

__global__ void transpose_comb(const float* __restrict__ comb_W) {
    int idx = blockIdx.x * blockDim.x + threadIdx.x;
    if (idx < 1024 * 512) {
        int n = idx >> 9, i = idx & 511;
        g_combWT[idx] = rtf(comb_W[(size_t)i * 1024 + n]);
    }
}

__global__ void roundWih_kernel(const float* __restrict__ Wih) {
    int idx = blockIdx.x * blockDim.x + threadIdx.x;
    if (idx < G3 * 512) g_WihR[idx] = rtf(Wih[idx]);
}

__global__ void convOutW_kernel(const float* __restrict__ outW) {
    int idx = blockIdx.x * blockDim.x + threadIdx.x;
    if (idx < VV * 512 / 4) {
        float4 v = ((const float4*)outW)[idx];
        int b = idx * 4;
        g_outWH[b + 0] = __float2half_rn(v.x);
        g_outWH[b + 1] = __float2half_rn(v.y);
        g_outWH[b + 2] = __float2half_rn(v.z);
        g_outWH[b + 3] = __float2half_rn(v.w);
    }
}

__global__ void biasg_kernel(const float* __restrict__ Wih,
                             const float* __restrict__ comb_b,
                             const float* __restrict__ bih) {
    int g = blockIdx.x;
    int tid = threadIdx.x;
    float s = 0.0f;
    for (int i = tid; i < 512; i += 128) s += Wih[(size_t)g * 512 + i] * comb_b[i];
    s = block_reduce_sum(s);
    if (tid == 0) g_bias0[512 + g] = s + bih[g];
}

__global__ void pack_kernel(const float* __restrict__ attn_W,
                            const float* __restrict__ gru_Whh,
                            const float* __restrict__ attn_b) {
    for (int idx = blockIdx.x * blockDim.x + threadIdx.x; idx < 2048 * 512;
         idx += gridDim.x * blockDim.x) {
        int j = idx >> 9, k = idx & 511;
        g_WpX[idx] = rtf((j < 512) ? attn_W[(size_t)j * 1024 + k]
                                   : g_Mmat[(size_t)(j - 512) * 1024 + k]);
        g_WpH[idx] = rtf((j < 512) ? attn_W[(size_t)j * 1024 + 512 + k]
                                   : gru_Whh[(size_t)(j - 512) * 512 + k]);
        if (j < G3) g_M2[idx] = rtf(g_Mmat[(size_t)j * 1024 + 512 + k]);
        if (idx < 512) g_bias0[idx] = attn_b[idx];
    }
}

__global__ void copyh_kernel(const float* __restrict__ src) {
    int i = blockIdx.x * blockDim.x + threadIdx.x;
    if (i < BB * HH) {
        float v = src[i];
        g_h[i]  = v;
        g_hR[i] = rtf(v);
    }
}

// fused logsumexp + apply (passes 2-3 hit L1: 40KB/row persists within launch)
__global__ void lse_apply(float* __restrict__ logits) {
    size_t base = (size_t)blockIdx.x * VV;
    float4* rv = (float4*)(logits + base);
    int tid = threadIdx.x;
    float m = -3.0e38f;
    for (int i = tid; i < VV / 4; i += 256) {
        float4 v = rv[i];
        m = fmaxf(m, fmaxf(fmaxf(v.x, v.y), fmaxf(v.z, v.w)));
    }
    m = block_reduce_max(m);
    float s = 0.0f;
    for (int i = tid; i < VV / 4; i += 256) {
        float4 v = rv[i];
        s += expf(v.x - m) + expf(v.y - m) + expf(v.z - m) + expf(v.w - m);
    }
    s = block_reduce_sum(s);
    float lse = m + logf(s);
    for (int i = tid; i < VV / 4; i += 256) {
        float4 v = rv[i];
        v.x -= lse; v.y -= lse; v.z -= lse; v.w -= lse;
        rv[i] = v;
    }
}

// ---------------- host driver -------------------------------------------------
template<typename Tp>
static void* symaddr(Tp& ref) {
    void* p = nullptr;
    cudaGetSymbolAddress(&p, ref);
    return p;
}

extern "C" void kernel_launch(void* const* d_in, const int* in_sizes, int n_in,
                              void* d_out, int out_size) {
    const float* features = (const float*)d_in[0];
    const int*   captions = (const int*)d_in[1];
    const float* h0       = (const float*)d_in[2];
    const float* embed_W  = (const float*)d_in[4];
    const float* fc_W     = (const float*)d_in[5];
    const float* fc_b     = (const float*)d_in[6];
    const float* bn_gamma = (const float*)d_in[7];
    const float* bn_beta  = (const float*)d_in[8];
    const float* attn_W   = (const float*)d_in[9];
    const float* attn_b   = (const float*)d_in[10];
    const float* comb_W   = (const float*)d_in[11];
    const float* comb_b   = (const float*)d_in[12];
    const float* gru_Wih  = (const float*)d_in[13];
    const float* gru_Whh  = (const float*)d_in[14];
    const float* gru_bih  = (const float*)d_in[15];
    const float* gru_bhh  = (const float*)d_in[16];
    const float* out_W    = (const float*)d_in[17];
    const float* out_b    = (const float*)d_in[18];

    float* out_logp = (float*)d_out;
    float* out_hid  = out_logp + (size_t)TT * BB * VV;

    float* p_fpre   = (float*)symaddr(g_fpre);
    float* p_X      = (float*)symaddr(g_X);
    float* p_P      = (float*)symaddr(g_P);
    float* p_combWT = (float*)symaddr(g_combWT);
    float* p_WihR   = (float*)symaddr(g_WihR);
    float* p_Mmat   = (float*)symaddr(g_Mmat);
    float* p_WpX    = (float*)symaddr(g_WpX);
    float* p_bias0  = (float*)symaddr(g_bias0);
    __half* p_hsH   = (__half*)symaddr(g_hsH);
    __half* p_outWH = (__half*)symaddr(g_outWH);

    const int GB_SMEM = 4 * 4608 * 4;                                   // 73728 B
    const int RK_SMEM = (16 * 516 + 24 * 516 + 2 * STG_BUF) * 4;        // 217728 B
    cudaFuncSetAttribute(gemm_big<0>, cudaFuncAttributeMaxDynamicSharedMemorySize, GB_SMEM);
    cudaFuncSetAttribute(gemm_big<1>, cudaFuncAttributeMaxDynamicSharedMemorySize, GB_SMEM);
    cudaFuncSetAttribute(recurrent_kernel, cudaFuncAttributeMaxDynamicSharedMemorySize, RK_SMEM);
    cudaFuncSetAttribute(gemm_fp16, cudaFuncAttributeMaxDynamicSharedMemorySize, HF_SMEM);

    // 0. comb_W^T (tf32)
    transpose_comb<<<(1024 * 512 + 255) / 256, 256>>>(comb_W);
    // 1. round gru_Wih
    roundWih_kernel<<<(G3 * 512 + 255) / 256, 256>>>(gru_Wih);
    // 2. fc (internal cvt.rna)
    gemm_tf32<64, 64, 32, 1><<<dim3(8, 2), 128>>>(
        features, fc_W, p_fpre, BB, EE, FIN, fc_b);
    // 3. Mmat = WihR @ combWT  <-- PROFILED SLOT
    gemm_big<0><<<dim3(8, 12), 256, GB_SMEM>>>(
        p_WihR, p_combWT, p_Mmat, G3, 1024, 512, nullptr);
    // 4. BatchNorm -> feats (full) + X[t=0] (tf32)
    bn_kernel<<<EE, BB>>>(p_fpre, bn_gamma, bn_beta);
    // 5. X[t>=1] (tf32)
    buildX_kernel<<<dim3(BB, TT - 1), 128>>>(captions, embed_W);
    // 6. out_W -> fp16
    convOutW_kernel<<<(VV * 512 / 4 + 255) / 256, 256>>>(out_W);
    // 7. gh bias (fp32)
    biasg_kernel<<<G3, 128>>>(gru_Wih, comb_b, gru_bih);
    // 8. pack (rounds WpX/WpH/M2)
    pack_kernel<<<2048, 512>>>(attn_W, gru_Whh, attn_b);
    // 9. P_all = X @ WpX^T + bias0
    gemm_big<1><<<dim3(16, 64), 256, GB_SMEM>>>(
        p_X, p_WpX, p_P, TT * BB, 2048, 512, p_bias0);
    // 10. h = h0 (full + rounded)
    copyh_kernel<<<(BB * HH + 255) / 256, 256>>>(h0);
    // 11. persistent recurrence
    recurrent_kernel<<<NBLK, 256, RK_SMEM>>>(gru_bhh, out_hid);
    // 12. logits = hsH @ outWH^T + out_b via fp16 mma
    gemm_fp16<<<dim3((VV + 127) / 128, (TT * BB) / 128), 256, HF_SMEM>>>(
        p_hsH, p_outWH, out_logp, TT * BB, VV, 512, out_b);
    // 13. fused log_softmax
    lse_apply<<<TT * BB, 256>>>(out_logp);
}